// round 2
// baseline (speedup 1.0000x reference)
#include <cuda_runtime.h>
#include <math.h>

#define SEQ    2048
#define BATCH  2
#define DIM    1024
#define HEADS  16
#define DH     64
#define MROWS  (BATCH*SEQ)          // 4096
#define QKVCOL (3*DIM)              // 3072

// Scratch (no allocation allowed) ------------------------------------------
__device__ float g_qkv [MROWS * QKVCOL];   // [4096, 3072]  (q | k | v)
__device__ float g_attn[MROWS * DIM];      // [4096, 1024]

// ---------------------------------------------------------------------------
// C[M,N] = A[M,K] @ B[N,K]^T   (both row-major; exact tiling, no bounds checks:
// M=4096, N in {3072,1024}, K=1024 all divisible by tile sizes)
// BM=BN=64, BK=16, 256 threads, 4x4 microtile per thread.
// ---------------------------------------------------------------------------
__global__ void __launch_bounds__(256) gemm_abt(const float* __restrict__ A,
                                                const float* __restrict__ B,
                                                float* __restrict__ C,
                                                int M, int N, int K)
{
    __shared__ float As[16][64];
    __shared__ float Bs[16][64];

    const int bm  = blockIdx.y * 64;
    const int bn  = blockIdx.x * 64;
    const int tid = threadIdx.x;
    const int tx  = tid & 15;     // 0..15 -> N microtile
    const int ty  = tid >> 4;     // 0..15 -> M microtile

    float acc[4][4] = {};

    for (int k0 = 0; k0 < K; k0 += 16) {
        // cooperative load: 64 rows x 16 k, one float4 per thread per matrix
        const int row = tid >> 2;          // 0..63
        const int kk4 = (tid & 3) * 4;     // 0,4,8,12
        float4 a4 = *reinterpret_cast<const float4*>(A + (size_t)(bm + row) * K + k0 + kk4);
        float4 b4 = *reinterpret_cast<const float4*>(B + (size_t)(bn + row) * K + k0 + kk4);
        As[kk4+0][row] = a4.x; As[kk4+1][row] = a4.y; As[kk4+2][row] = a4.z; As[kk4+3][row] = a4.w;
        Bs[kk4+0][row] = b4.x; Bs[kk4+1][row] = b4.y; Bs[kk4+2][row] = b4.z; Bs[kk4+3][row] = b4.w;
        __syncthreads();

        #pragma unroll
        for (int kk = 0; kk < 16; kk++) {
            float ar[4], br[4];
            #pragma unroll
            for (int i = 0; i < 4; i++) ar[i] = As[kk][ty*4 + i];
            #pragma unroll
            for (int j = 0; j < 4; j++) br[j] = Bs[kk][tx*4 + j];
            #pragma unroll
            for (int i = 0; i < 4; i++)
                #pragma unroll
                for (int j = 0; j < 4; j++)
                    acc[i][j] += ar[i] * br[j];
        }
        __syncthreads();
    }

    #pragma unroll
    for (int i = 0; i < 4; i++) {
        #pragma unroll
        for (int j = 0; j < 4; j++)
            C[(size_t)(bm + ty*4 + i) * N + bn + tx*4 + j] = acc[i][j];
    }
}

// ---------------------------------------------------------------------------
// Causal flash attention, fp32. One block = one (b,h) x 128-query tile.
// 128 threads, each owns one query row (q + 64 accumulators in registers).
// K/V tiles of 64 rows in dynamic smem; scores staged in padded smem.
// ---------------------------------------------------------------------------
__global__ void __launch_bounds__(128) attn_kernel(const float* __restrict__ qkv,
                                                   float* __restrict__ outp)
{
    extern __shared__ float smem[];
    float* Ks = smem;               // [64][64]
    float* Vs = smem + 64*64;       // [64][64]
    float* SC = smem + 2*64*64;     // [128][65] padded scores

    const int bh  = blockIdx.y;           // 0..31
    const int b   = bh >> 4;
    const int h   = bh & 15;
    const int q0  = blockIdx.x * 128;
    const int tid = threadIdx.x;
    const int qi  = q0 + tid;             // global query index

    const float* base = qkv + (size_t)b * SEQ * QKVCOL;

    // load my query row, pre-scaled by 1/sqrt(64)
    float q[DH];
    {
        const float* qr = base + (size_t)qi * QKVCOL + h * DH;
        #pragma unroll
        for (int d = 0; d < DH; d++) q[d] = qr[d] * 0.125f;
    }

    float acc[DH] = {};
    float mrun = -INFINITY;
    float lrun = 0.f;

    const int ntiles = q0 / 64 + 2;       // keys [0, q0+128)

    for (int t = 0; t < ntiles; t++) {
        const int ks = t * 64;
        // load K,V tile: 64 rows x 64 cols, 128 threads -> each does 8 float4 per matrix
        {
            const int r  = tid >> 1;
            const int c0 = (tid & 1) * 32;
            const float* kr = base + (size_t)(ks + r) * QKVCOL +     DIM + h * DH + c0;
            const float* vr = base + (size_t)(ks + r) * QKVCOL + 2 * DIM + h * DH + c0;
            float4*       kd = reinterpret_cast<float4*>(&Ks[r*DH + c0]);
            float4*       vd = reinterpret_cast<float4*>(&Vs[r*DH + c0]);
            #pragma unroll
            for (int i = 0; i < 8; i++) {
                kd[i] = reinterpret_cast<const float4*>(kr)[i];
                vd[i] = reinterpret_cast<const float4*>(vr)[i];
            }
        }
        __syncthreads();

        // scores for this tile
        float tmax = mrun;
        #pragma unroll 4
        for (int j = 0; j < 64; j++) {
            float s = 0.f;
            #pragma unroll
            for (int d = 0; d < DH; d++) s += q[d] * Ks[j*DH + d];
            if (ks + j > qi) s = -INFINITY;
            SC[tid*65 + j] = s;
            tmax = fmaxf(tmax, s);
        }

        const float corr = __expf(mrun - tmax);   // 0 on first tile (mrun=-inf, tmax finite)
        mrun = tmax;
        lrun *= corr;
        #pragma unroll
        for (int d = 0; d < DH; d++) acc[d] *= corr;

        #pragma unroll 2
        for (int j = 0; j < 64; j++) {
            const float p = __expf(SC[tid*65 + j] - mrun);
            lrun += p;
            #pragma unroll
            for (int d = 0; d < DH; d++) acc[d] += p * Vs[j*DH + d];
        }
        __syncthreads();
    }

    const float inv = 1.f / lrun;
    float* orow = outp + (size_t)(b * SEQ + qi) * DIM + h * DH;
    #pragma unroll
    for (int d = 0; d < DH; d += 4) {
        float4 v = make_float4(acc[d]*inv, acc[d+1]*inv, acc[d+2]*inv, acc[d+3]*inv);
        *reinterpret_cast<float4*>(orow + d) = v;
    }
}

// ---------------------------------------------------------------------------
extern "C" void kernel_launch(void* const* d_in, const int* in_sizes, int n_in,
                              void* d_out, int out_size)
{
    const float* x     = (const float*)d_in[0];   // [2,2048,1024]
    const float* W_qkv = (const float*)d_in[1];   // [3072,1024]
    const float* W_out = (const float*)d_in[2];   // [1024,1024]
    float*       out   = (float*)d_out;           // [2,2048,1024]

    float* qkv  = nullptr;
    float* attn = nullptr;
    cudaGetSymbolAddress((void**)&qkv,  g_qkv);
    cudaGetSymbolAddress((void**)&attn, g_attn);

    const int ATTN_SMEM = (64*64 + 64*64 + 128*65) * (int)sizeof(float);  // 66048 B
    cudaFuncSetAttribute(attn_kernel, cudaFuncAttributeMaxDynamicSharedMemorySize, ATTN_SMEM);

    // 1) qkv = x @ W_qkv^T : [4096,1024] x [3072,1024]^T -> [4096,3072]
    gemm_abt<<<dim3(QKVCOL/64, MROWS/64), 256>>>(x, W_qkv, qkv, MROWS, QKVCOL, DIM);

    // 2) causal attention -> g_attn [4096,1024]
    attn_kernel<<<dim3(SEQ/128, BATCH*HEADS), 128, ATTN_SMEM>>>(qkv, attn);

    // 3) out = attn @ W_out^T : [4096,1024] x [1024,1024]^T -> [4096,1024]
    gemm_abt<<<dim3(DIM/64, MROWS/64), 256>>>(attn, W_out, out, MROWS, DIM, DIM);
}

// round 3
// speedup vs baseline: 3.0157x; 3.0157x over previous
#include <cuda_runtime.h>
#include <math.h>
#include <stdint.h>

#define SEQ    2048
#define BATCH  2
#define DIM    1024
#define HEADS  16
#define DH     64
#define MROWS  (BATCH*SEQ)          // 4096
#define QKVCOL (3*DIM)              // 3072

__device__ float g_qkv [MROWS * QKVCOL];
__device__ float g_attn[MROWS * DIM];

// ---------------------------------------------------------------------------
__device__ __forceinline__ uint32_t f2tf(float x){
    uint32_t r; asm("cvt.rna.tf32.f32 %0, %1;" : "=r"(r) : "f"(x)); return r;
}
__device__ __forceinline__ void mma8(float* c, const uint32_t* a, const uint32_t* b){
    asm volatile("mma.sync.aligned.m16n8k8.row.col.f32.tf32.tf32.f32 "
        "{%0,%1,%2,%3}, {%4,%5,%6,%7}, {%8,%9}, {%0,%1,%2,%3};"
        : "+f"(c[0]),"+f"(c[1]),"+f"(c[2]),"+f"(c[3])
        : "r"(a[0]),"r"(a[1]),"r"(a[2]),"r"(a[3]),"r"(b[0]),"r"(b[1]));
}

// ---------------------------------------------------------------------------
// C[M,N] = A[M,K] @ B[N,K]^T, tf32 tensor cores.
// 128x128x16 block tile, 256 threads, warp tile 64x32 (2x4 warp grid).
// ---------------------------------------------------------------------------
#define GBM 128
#define GBN 128
#define GBK 16
#define GST 20          // smem row stride (floats): conflict-free frag loads

__global__ void __launch_bounds__(256,2) gemm_tf32(const float* __restrict__ A,
                                                   const float* __restrict__ B,
                                                   float* __restrict__ C,
                                                   int M, int N, int K)
{
    __shared__ uint32_t As[2][GBM*GST];
    __shared__ uint32_t Bs[2][GBN*GST];

    const int tid  = threadIdx.x;
    const int lane = tid & 31, wid = tid >> 5;
    const int g = lane >> 2, t = lane & 3;
    const int wm = wid & 1;        // 0..1  -> 64-row band
    const int wn = wid >> 1;       // 0..3  -> 32-col band
    const int bm = blockIdx.y * GBM, bn = blockIdx.x * GBN;

    const int lrow = tid >> 1;                 // 0..127
    const int loff = (tid & 1) * 8;            // k offset 0 or 8

    const float* Ag = A + (size_t)(bm + lrow) * K + loff;
    const float* Bg = B + (size_t)(bn + lrow) * K + loff;

    float acc[4][4][4] = {};

    // preload tile 0
    {
        float4 a0 = *(const float4*)(Ag);
        float4 a1 = *(const float4*)(Ag + 4);
        float4 b0 = *(const float4*)(Bg);
        float4 b1 = *(const float4*)(Bg + 4);
        uint4* as = (uint4*)&As[0][lrow*GST + loff];
        uint4* bs = (uint4*)&Bs[0][lrow*GST + loff];
        as[0] = make_uint4(f2tf(a0.x),f2tf(a0.y),f2tf(a0.z),f2tf(a0.w));
        as[1] = make_uint4(f2tf(a1.x),f2tf(a1.y),f2tf(a1.z),f2tf(a1.w));
        bs[0] = make_uint4(f2tf(b0.x),f2tf(b0.y),f2tf(b0.z),f2tf(b0.w));
        bs[1] = make_uint4(f2tf(b1.x),f2tf(b1.y),f2tf(b1.z),f2tf(b1.w));
    }
    __syncthreads();

    int buf = 0;
    for (int k0 = 0; k0 < K; k0 += GBK) {
        const bool more = (k0 + GBK) < K;
        float4 pa0, pa1, pb0, pb1;
        if (more) {
            pa0 = *(const float4*)(Ag + k0 + GBK);
            pa1 = *(const float4*)(Ag + k0 + GBK + 4);
            pb0 = *(const float4*)(Bg + k0 + GBK);
            pb1 = *(const float4*)(Bg + k0 + GBK + 4);
        }

        #pragma unroll
        for (int ks = 0; ks < 2; ks++) {
            uint32_t af[4][4], bf[4][2];
            #pragma unroll
            for (int ma = 0; ma < 4; ma++) {
                const int r0 = (wm*64 + ma*16 + g)*GST + ks*8 + t;
                af[ma][0] = As[buf][r0];
                af[ma][1] = As[buf][r0 + 8*GST];
                af[ma][2] = As[buf][r0 + 4];
                af[ma][3] = As[buf][r0 + 8*GST + 4];
            }
            #pragma unroll
            for (int nb = 0; nb < 4; nb++) {
                const int r = (wn*32 + nb*8 + g)*GST + ks*8 + t;
                bf[nb][0] = Bs[buf][r];
                bf[nb][1] = Bs[buf][r + 4];
            }
            #pragma unroll
            for (int ma = 0; ma < 4; ma++)
                #pragma unroll
                for (int nb = 0; nb < 4; nb++)
                    mma8(acc[ma][nb], af[ma], bf[nb]);
        }

        if (more) {
            uint4* as = (uint4*)&As[buf^1][lrow*GST + loff];
            uint4* bs = (uint4*)&Bs[buf^1][lrow*GST + loff];
            as[0] = make_uint4(f2tf(pa0.x),f2tf(pa0.y),f2tf(pa0.z),f2tf(pa0.w));
            as[1] = make_uint4(f2tf(pa1.x),f2tf(pa1.y),f2tf(pa1.z),f2tf(pa1.w));
            bs[0] = make_uint4(f2tf(pb0.x),f2tf(pb0.y),f2tf(pb0.z),f2tf(pb0.w));
            bs[1] = make_uint4(f2tf(pb1.x),f2tf(pb1.y),f2tf(pb1.z),f2tf(pb1.w));
            __syncthreads();
            buf ^= 1;
        }
    }

    #pragma unroll
    for (int ma = 0; ma < 4; ma++) {
        const int r0 = bm + wm*64 + ma*16 + g;
        #pragma unroll
        for (int nb = 0; nb < 4; nb++) {
            const int c0 = bn + wn*32 + nb*8 + 2*t;
            *(float2*)&C[(size_t)r0      * N + c0] = make_float2(acc[ma][nb][0], acc[ma][nb][1]);
            *(float2*)&C[(size_t)(r0+8)  * N + c0] = make_float2(acc[ma][nb][2], acc[ma][nb][3]);
        }
    }
}

// ---------------------------------------------------------------------------
// Flash attention, tf32 tensor cores. Block = 128 queries of one (b,h).
// 8 warps x 16 query rows. Key/value tiles of 64 in smem (stride 72).
// Q resident in registers as tf32 A-fragments. Causal, online softmax.
// ---------------------------------------------------------------------------
#define AT 72

__global__ void __launch_bounds__(256) attn_tf32(const float* __restrict__ qkv,
                                                 float* __restrict__ outp)
{
    __shared__ uint32_t sh[2*64*AT];            // 9216 words; also Q staging
    float*    Qs = (float*)sh;                  // [128][AT]
    uint32_t* Ks = sh;                          // [64][AT]
    uint32_t* Vs = sh + 64*AT;                  // [64][AT]

    const int tid = threadIdx.x;
    const int lane = tid & 31, wid = tid >> 5;
    const int g = lane >> 2, t = lane & 3;
    const int bh = blockIdx.y, b = bh >> 4, h = bh & 15;
    const int q0 = blockIdx.x * 128;
    const float* base = qkv + (size_t)b * SEQ * QKVCOL;

    // stage Q (raw fp32) into smem
    {
        const int r = tid >> 1, f0 = (tid & 1) * 32;
        const float* qr = base + (size_t)(q0 + r) * QKVCOL + h*DH + f0;
        float* dst = Qs + r*AT + f0;
        #pragma unroll
        for (int i = 0; i < 8; i++)
            ((float4*)dst)[i] = ((const float4*)qr)[i];
    }
    __syncthreads();

    // extract Q fragments (scaled by 1/sqrt(64), rounded to tf32)
    uint32_t qf[8][4];
    {
        const float* qb = Qs + (wid*16 + g) * AT;
        #pragma unroll
        for (int kk = 0; kk < 8; kk++) {
            qf[kk][0] = f2tf(qb[kk*8 + t]           * 0.125f);
            qf[kk][1] = f2tf(qb[8*AT + kk*8 + t]    * 0.125f);
            qf[kk][2] = f2tf(qb[kk*8 + t + 4]       * 0.125f);
            qf[kk][3] = f2tf(qb[8*AT + kk*8 + t + 4]* 0.125f);
        }
    }
    __syncthreads();

    float o[8][4] = {};
    float m0 = -INFINITY, m1 = -INFINITY, l0 = 0.f, l1 = 0.f;
    const int row0 = q0 + wid*16 + g;
    const int ntiles = q0/64 + 2;

    for (int kt = 0; kt < ntiles; kt++) {
        // load K/V tile, converting to tf32
        {
            const int r = tid >> 2, c0 = (tid & 3) * 16;
            const float* kr = base + (size_t)(kt*64 + r) * QKVCOL +     DIM + h*DH + c0;
            const float* vr = base + (size_t)(kt*64 + r) * QKVCOL + 2 * DIM + h*DH + c0;
            uint32_t* kd = Ks + r*AT + c0;
            uint32_t* vd = Vs + r*AT + c0;
            #pragma unroll
            for (int i = 0; i < 4; i++) {
                float4 kv = ((const float4*)kr)[i];
                float4 vv = ((const float4*)vr)[i];
                ((uint4*)kd)[i] = make_uint4(f2tf(kv.x),f2tf(kv.y),f2tf(kv.z),f2tf(kv.w));
                ((uint4*)vd)[i] = make_uint4(f2tf(vv.x),f2tf(vv.y),f2tf(vv.z),f2tf(vv.w));
            }
        }
        __syncthreads();

        // ---- S = Q @ K^T (warp tile 16x64) ----
        float s[8][4] = {};
        #pragma unroll
        for (int kk = 0; kk < 8; kk++) {
            uint32_t bk[8][2];
            #pragma unroll
            for (int na = 0; na < 8; na++) {
                const int idx = (na*8 + g)*AT + kk*8 + t;
                bk[na][0] = Ks[idx];
                bk[na][1] = Ks[idx + 4];
            }
            #pragma unroll
            for (int na = 0; na < 8; na++)
                mma8(s[na], qf[kk], bk[na]);
        }

        // ---- causal mask + online softmax (rows g and g+8) ----
        const int colbase = kt*64 + 2*t;
        float t0 = -INFINITY, t1 = -INFINITY;
        #pragma unroll
        for (int na = 0; na < 8; na++) {
            const int c = colbase + na*8;
            if (c     > row0)     s[na][0] = -INFINITY;
            if (c + 1 > row0)     s[na][1] = -INFINITY;
            if (c     > row0 + 8) s[na][2] = -INFINITY;
            if (c + 1 > row0 + 8) s[na][3] = -INFINITY;
            t0 = fmaxf(t0, fmaxf(s[na][0], s[na][1]));
            t1 = fmaxf(t1, fmaxf(s[na][2], s[na][3]));
        }
        t0 = fmaxf(t0, __shfl_xor_sync(0xffffffffu, t0, 1));
        t0 = fmaxf(t0, __shfl_xor_sync(0xffffffffu, t0, 2));
        t1 = fmaxf(t1, __shfl_xor_sync(0xffffffffu, t1, 1));
        t1 = fmaxf(t1, __shfl_xor_sync(0xffffffffu, t1, 2));

        const float mn0 = fmaxf(m0, t0), mn1 = fmaxf(m1, t1);
        const float sc0 = __expf(m0 - mn0), sc1 = __expf(m1 - mn1);
        m0 = mn0; m1 = mn1; l0 *= sc0; l1 *= sc1;

        #pragma unroll
        for (int na = 0; na < 8; na++) {
            o[na][0] *= sc0; o[na][1] *= sc0; o[na][2] *= sc1; o[na][3] *= sc1;
            s[na][0] = __expf(s[na][0] - m0);
            s[na][1] = __expf(s[na][1] - m0);
            s[na][2] = __expf(s[na][2] - m1);
            s[na][3] = __expf(s[na][3] - m1);
            l0 += s[na][0] + s[na][1];
            l1 += s[na][2] + s[na][3];
        }

        // ---- O += P @ V (P frags built via intra-quad shuffles) ----
        #pragma unroll
        for (int kk = 0; kk < 8; kk++) {
            const int srcA = (lane & ~3) | (t >> 1);
            const int srcB = srcA + 2;
            float y0 = __shfl_sync(0xffffffffu, s[kk][0], srcA);
            float y1 = __shfl_sync(0xffffffffu, s[kk][1], srcA);
            float y2 = __shfl_sync(0xffffffffu, s[kk][2], srcA);
            float y3 = __shfl_sync(0xffffffffu, s[kk][3], srcA);
            float z0 = __shfl_sync(0xffffffffu, s[kk][0], srcB);
            float z1 = __shfl_sync(0xffffffffu, s[kk][1], srcB);
            float z2 = __shfl_sync(0xffffffffu, s[kk][2], srcB);
            float z3 = __shfl_sync(0xffffffffu, s[kk][3], srcB);
            uint32_t pa[4];
            pa[0] = f2tf((t & 1) ? y1 : y0);
            pa[1] = f2tf((t & 1) ? y3 : y2);
            pa[2] = f2tf((t & 1) ? z1 : z0);
            pa[3] = f2tf((t & 1) ? z3 : z2);
            #pragma unroll
            for (int na = 0; na < 8; na++) {
                uint32_t bv[2];
                const int idx = (kk*8 + t)*AT + na*8 + g;
                bv[0] = Vs[idx];
                bv[1] = Vs[idx + 4*AT];
                mma8(o[na], pa, bv);
            }
        }
        __syncthreads();
    }

    // ---- finalize ----
    l0 += __shfl_xor_sync(0xffffffffu, l0, 1);
    l0 += __shfl_xor_sync(0xffffffffu, l0, 2);
    l1 += __shfl_xor_sync(0xffffffffu, l1, 1);
    l1 += __shfl_xor_sync(0xffffffffu, l1, 2);
    const float i0 = 1.f / l0, i1 = 1.f / l1;

    float* orow0 = outp + (size_t)(b*SEQ + row0) * DIM + h*DH;
    float* orow1 = orow0 + 8*DIM;
    #pragma unroll
    for (int na = 0; na < 8; na++) {
        *(float2*)&orow0[na*8 + 2*t] = make_float2(o[na][0]*i0, o[na][1]*i0);
        *(float2*)&orow1[na*8 + 2*t] = make_float2(o[na][2]*i1, o[na][3]*i1);
    }
}

// ---------------------------------------------------------------------------
extern "C" void kernel_launch(void* const* d_in, const int* in_sizes, int n_in,
                              void* d_out, int out_size)
{
    const float* x     = (const float*)d_in[0];
    const float* W_qkv = (const float*)d_in[1];
    const float* W_out = (const float*)d_in[2];
    float*       out   = (float*)d_out;

    float* qkv  = nullptr;
    float* attn = nullptr;
    cudaGetSymbolAddress((void**)&qkv,  g_qkv);
    cudaGetSymbolAddress((void**)&attn, g_attn);

    // 1) qkv = x @ W_qkv^T
    gemm_tf32<<<dim3(QKVCOL/GBN, MROWS/GBM), 256>>>(x, W_qkv, qkv, MROWS, QKVCOL, DIM);
    // 2) causal attention
    attn_tf32<<<dim3(SEQ/128, BATCH*HEADS), 256>>>(qkv, attn);
    // 3) out = attn @ W_out^T
    gemm_tf32<<<dim3(DIM/GBN, MROWS/GBM), 256>>>(attn, W_out, out, MROWS, DIM, DIM);
}

// round 6
// speedup vs baseline: 3.1247x; 1.0361x over previous
#include <cuda_runtime.h>
#include <math.h>
#include <stdint.h>

#define SEQ    2048
#define BATCH  2
#define DIM    1024
#define HEADS  16
#define DH     64
#define MROWS  (BATCH*SEQ)          // 4096
#define QKVCOL (3*DIM)              // 3072

__device__ float g_qkv [MROWS * QKVCOL];
__device__ float g_attn[MROWS * DIM];

// ---------------------------------------------------------------------------
__device__ __forceinline__ uint32_t f2tf(float x){
    uint32_t r; asm("cvt.rna.tf32.f32 %0, %1;" : "=r"(r) : "f"(x)); return r;
}
__device__ __forceinline__ uint32_t smem_u32(const void* p){
    return (uint32_t)__cvta_generic_to_shared(p);
}
__device__ __forceinline__ void mma8(float* c, const uint32_t* a, const uint32_t* b){
    asm volatile("mma.sync.aligned.m16n8k8.row.col.f32.tf32.tf32.f32 "
        "{%0,%1,%2,%3}, {%4,%5,%6,%7}, {%8,%9}, {%0,%1,%2,%3};"
        : "+f"(c[0]),"+f"(c[1]),"+f"(c[2]),"+f"(c[3])
        : "r"(a[0]),"r"(a[1]),"r"(a[2]),"r"(a[3]),"r"(b[0]),"r"(b[1]));
}
__device__ __forceinline__ void ldsm4(uint32_t& r0, uint32_t& r1, uint32_t& r2, uint32_t& r3,
                                      uint32_t addr){
    asm volatile("ldmatrix.sync.aligned.m8n8.x4.shared.b16 {%0,%1,%2,%3}, [%4];"
        : "=r"(r0),"=r"(r1),"=r"(r2),"=r"(r3) : "r"(addr));
}

// ---------------------------------------------------------------------------
// tf32 GEMM: C[M,N] = A[M,K] @ B[N,K]^T.
// CTA tile 128x128, 4 warps (2x2), warp tile 64x64. ldmatrix fragment loads.
// ---------------------------------------------------------------------------
#define GST 20          // smem row stride in words; conflict-free for LDSM & STS

__global__ void __launch_bounds__(128) gemm_lds(const float* __restrict__ A,
                                                const float* __restrict__ B,
                                                float* __restrict__ C,
                                                int M, int N, int K)
{
    __shared__ uint32_t As[2][128*GST];
    __shared__ uint32_t Bs[2][128*GST];

    const int tid  = threadIdx.x;
    const int lane = tid & 31, wid = tid >> 5;
    const int g = lane >> 2, t = lane & 3;
    const int wm = wid & 1, wn = wid >> 1;
    const int bm = blockIdx.y * 128, bn = blockIdx.x * 128;

    const uint32_t As0 = smem_u32(As), Bs0 = smem_u32(Bs);
    // per-lane ldmatrix byte offsets
    const uint32_t a_lo = ((((lane & 7) + ((lane >> 3) & 1) * 8) * GST) + (lane >> 4) * 4) * 4;
    const uint32_t b_lo = ((((lane & 7) + ((lane >> 4) & 1) * 8) * GST) + ((lane >> 3) & 1) * 4) * 4;

    // fill mapping: thread owns one row, 16 k-floats (4 float4)
    const float* Ag = A + (size_t)(bm + tid) * K;
    const float* Bg = B + (size_t)(bn + tid) * K;
    const uint32_t sA = As0 + (uint32_t)(tid * GST) * 4;
    const uint32_t sB = Bs0 + (uint32_t)(tid * GST) * 4;

    float acc[4][8][4] = {};
    const int NC = K / 16;

    float4 ra[4], rb[4];
    #pragma unroll
    for (int i = 0; i < 4; i++) { ra[i] = ((const float4*)Ag)[i]; rb[i] = ((const float4*)Bg)[i]; }
    #pragma unroll
    for (int i = 0; i < 4; i++) {
        asm volatile("st.shared.v4.b32 [%0], {%1,%2,%3,%4};" :: "r"(sA + i*16),
            "r"(f2tf(ra[i].x)),"r"(f2tf(ra[i].y)),"r"(f2tf(ra[i].z)),"r"(f2tf(ra[i].w)));
        asm volatile("st.shared.v4.b32 [%0], {%1,%2,%3,%4};" :: "r"(sB + i*16),
            "r"(f2tf(rb[i].x)),"r"(f2tf(rb[i].y)),"r"(f2tf(rb[i].z)),"r"(f2tf(rb[i].w)));
    }
    __syncthreads();

    for (int c = 0; c < NC; c++) {
        const int buf = c & 1;
        const uint32_t abase = As0 + (uint32_t)buf * (128*GST*4) + (uint32_t)(wm * 64 * GST) * 4;
        const uint32_t bbase = Bs0 + (uint32_t)buf * (128*GST*4) + (uint32_t)(wn * 64 * GST) * 4;

        if (c + 1 < NC) {
            const float* Ag2 = Ag + (c + 1) * 16;
            const float* Bg2 = Bg + (c + 1) * 16;
            #pragma unroll
            for (int i = 0; i < 4; i++) { ra[i] = ((const float4*)Ag2)[i]; rb[i] = ((const float4*)Bg2)[i]; }
        }

        #pragma unroll
        for (int ks = 0; ks < 2; ks++) {
            uint32_t af[4][4], bf[8][2];
            #pragma unroll
            for (int ma = 0; ma < 4; ma++)
                ldsm4(af[ma][0], af[ma][1], af[ma][2], af[ma][3],
                      abase + (uint32_t)(ma * 16 * GST + ks * 8) * 4 + a_lo);
            #pragma unroll
            for (int p = 0; p < 4; p++)
                ldsm4(bf[2*p][0], bf[2*p][1], bf[2*p+1][0], bf[2*p+1][1],
                      bbase + (uint32_t)(p * 16 * GST + ks * 8) * 4 + b_lo);
            #pragma unroll
            for (int ma = 0; ma < 4; ma++)
                #pragma unroll
                for (int nb = 0; nb < 8; nb++)
                    mma8(acc[ma][nb], af[ma], bf[nb]);
        }

        if (c + 1 < NC) {
            const uint32_t dA = sA + (uint32_t)((buf ^ 1) * 128 * GST) * 4;
            const uint32_t dB = sB + (uint32_t)((buf ^ 1) * 128 * GST) * 4;
            #pragma unroll
            for (int i = 0; i < 4; i++) {
                asm volatile("st.shared.v4.b32 [%0], {%1,%2,%3,%4};" :: "r"(dA + i*16),
                    "r"(f2tf(ra[i].x)),"r"(f2tf(ra[i].y)),"r"(f2tf(ra[i].z)),"r"(f2tf(ra[i].w)));
                asm volatile("st.shared.v4.b32 [%0], {%1,%2,%3,%4};" :: "r"(dB + i*16),
                    "r"(f2tf(rb[i].x)),"r"(f2tf(rb[i].y)),"r"(f2tf(rb[i].z)),"r"(f2tf(rb[i].w)));
            }
        }
        __syncthreads();
    }

    #pragma unroll
    for (int ma = 0; ma < 4; ma++) {
        const int r0 = bm + wm*64 + ma*16 + g;
        #pragma unroll
        for (int nb = 0; nb < 8; nb++) {
            const int c0 = bn + wn*64 + nb*8 + 2*t;
            *(float2*)&C[(size_t)r0     * N + c0] = make_float2(acc[ma][nb][0], acc[ma][nb][1]);
            *(float2*)&C[(size_t)(r0+8) * N + c0] = make_float2(acc[ma][nb][2], acc[ma][nb][3]);
        }
    }
}

// ---------------------------------------------------------------------------
// Flash attention, tf32 mma.sync + ldmatrix fragment loads.
// 256 threads (8 warps x 16 q-rows), KV tiles of 64. V stored transposed.
// ---------------------------------------------------------------------------
#define KST 68          // stride: 4r mod 32 pattern -> conflict-free LDSM

__global__ void __launch_bounds__(256) attn_tf32(const float* __restrict__ qkv,
                                                 float* __restrict__ outp)
{
    __shared__ uint32_t sh[2*64*KST];           // 34816 B; also Q staging (128*KST)
    float*    Qs = (float*)sh;
    uint32_t* Ks = sh;                          // [64 kv][KST]  (kv-major, d cols)
    uint32_t* Vt = sh + 64*KST;                 // [64 dh][KST]  (dh-major, kv cols)

    const int tid = threadIdx.x;
    const int lane = tid & 31, wid = tid >> 5;
    const int g = lane >> 2, t = lane & 3;
    const int bh = blockIdx.y, b = bh >> 4, h = bh & 15;
    const int q0 = blockIdx.x * 128;
    const float* base = qkv + (size_t)b * SEQ * QKVCOL;

    const uint32_t Ks0 = smem_u32(Ks), Vt0 = smem_u32(Vt);
    const uint32_t f_lo = ((((lane & 7) + ((lane >> 4) & 1) * 8) * KST) + ((lane >> 3) & 1) * 4) * 4;

    // stage Q raw into smem
    {
        const int r = tid >> 1, f0 = (tid & 1) * 32;
        const float* qr = base + (size_t)(q0 + r) * QKVCOL + h*DH + f0;
        float* dst = Qs + r*KST + f0;
        #pragma unroll
        for (int i = 0; i < 8; i++) ((float4*)dst)[i] = ((const float4*)qr)[i];
    }
    __syncthreads();

    // extract Q fragments (scaled, tf32)
    uint32_t qf[8][4];
    {
        const float* qb = Qs + (wid*16 + g) * KST;
        #pragma unroll
        for (int kk = 0; kk < 8; kk++) {
            qf[kk][0] = f2tf(qb[kk*8 + t]             * 0.125f);
            qf[kk][1] = f2tf(qb[8*KST + kk*8 + t]     * 0.125f);
            qf[kk][2] = f2tf(qb[kk*8 + t + 4]         * 0.125f);
            qf[kk][3] = f2tf(qb[8*KST + kk*8 + t + 4] * 0.125f);
        }
    }
    __syncthreads();

    float o[8][4] = {};
    float m0 = -INFINITY, m1 = -INFINITY, l0 = 0.f, l1 = 0.f;
    const int row0 = q0 + wid*16 + g;
    const int ntiles = q0/64 + 2;

    for (int kt = 0; kt < ntiles; kt++) {
        // fill K (kv-major) and V transposed (dh-major), tf32-converted
        {
            const int r = tid & 63, c0 = (tid >> 6) * 16;
            const float* kr = base + (size_t)(kt*64 + r) * QKVCOL +     DIM + h*DH + c0;
            const float* vr = base + (size_t)(kt*64 + r) * QKVCOL + 2 * DIM + h*DH + c0;
            uint32_t* kd = Ks + r*KST + c0;
            #pragma unroll
            for (int i = 0; i < 4; i++) {
                float4 kv = ((const float4*)kr)[i];
                ((uint4*)kd)[i] = make_uint4(f2tf(kv.x),f2tf(kv.y),f2tf(kv.z),f2tf(kv.w));
                float4 vv = ((const float4*)vr)[i];
                Vt[(c0 + 4*i    )*KST + r] = f2tf(vv.x);
                Vt[(c0 + 4*i + 1)*KST + r] = f2tf(vv.y);
                Vt[(c0 + 4*i + 2)*KST + r] = f2tf(vv.z);
                Vt[(c0 + 4*i + 3)*KST + r] = f2tf(vv.w);
            }
        }
        __syncthreads();

        // ---- S = Q @ K^T via ldmatrix b-frags ----
        float s[8][4] = {};
        #pragma unroll
        for (int kk = 0; kk < 8; kk++) {
            uint32_t bk[8][2];
            #pragma unroll
            for (int p = 0; p < 4; p++)
                ldsm4(bk[2*p][0], bk[2*p][1], bk[2*p+1][0], bk[2*p+1][1],
                      Ks0 + (uint32_t)(p * 16 * KST + kk * 8) * 4 + f_lo);
            #pragma unroll
            for (int nb = 0; nb < 8; nb++)
                mma8(s[nb], qf[kk], bk[nb]);
        }

        // ---- causal mask + online softmax ----
        const int colbase = kt*64 + 2*t;
        float t0 = -INFINITY, t1 = -INFINITY;
        #pragma unroll
        for (int na = 0; na < 8; na++) {
            const int c = colbase + na*8;
            if (c     > row0)     s[na][0] = -INFINITY;
            if (c + 1 > row0)     s[na][1] = -INFINITY;
            if (c     > row0 + 8) s[na][2] = -INFINITY;
            if (c + 1 > row0 + 8) s[na][3] = -INFINITY;
            t0 = fmaxf(t0, fmaxf(s[na][0], s[na][1]));
            t1 = fmaxf(t1, fmaxf(s[na][2], s[na][3]));
        }
        t0 = fmaxf(t0, __shfl_xor_sync(0xffffffffu, t0, 1));
        t0 = fmaxf(t0, __shfl_xor_sync(0xffffffffu, t0, 2));
        t1 = fmaxf(t1, __shfl_xor_sync(0xffffffffu, t1, 1));
        t1 = fmaxf(t1, __shfl_xor_sync(0xffffffffu, t1, 2));

        const float mn0 = fmaxf(m0, t0), mn1 = fmaxf(m1, t1);
        const float sc0 = __expf(m0 - mn0), sc1 = __expf(m1 - mn1);
        m0 = mn0; m1 = mn1; l0 *= sc0; l1 *= sc1;

        #pragma unroll
        for (int na = 0; na < 8; na++) {
            o[na][0] *= sc0; o[na][1] *= sc0; o[na][2] *= sc1; o[na][3] *= sc1;
            s[na][0] = __expf(s[na][0] - m0);
            s[na][1] = __expf(s[na][1] - m0);
            s[na][2] = __expf(s[na][2] - m1);
            s[na][3] = __expf(s[na][3] - m1);
            l0 += s[na][0] + s[na][1];
            l1 += s[na][2] + s[na][3];
        }

        // ---- O += P @ V : P a-frags via quad shuffles, V b-frags via ldmatrix ----
        #pragma unroll
        for (int kk = 0; kk < 8; kk++) {
            const int srcA = (lane & ~3) | (t >> 1);
            const int srcB = srcA + 2;
            float y0 = __shfl_sync(0xffffffffu, s[kk][0], srcA);
            float y1 = __shfl_sync(0xffffffffu, s[kk][1], srcA);
            float y2 = __shfl_sync(0xffffffffu, s[kk][2], srcA);
            float y3 = __shfl_sync(0xffffffffu, s[kk][3], srcA);
            float z0 = __shfl_sync(0xffffffffu, s[kk][0], srcB);
            float z1 = __shfl_sync(0xffffffffu, s[kk][1], srcB);
            float z2 = __shfl_sync(0xffffffffu, s[kk][2], srcB);
            float z3 = __shfl_sync(0xffffffffu, s[kk][3], srcB);
            uint32_t pa[4];
            pa[0] = f2tf((t & 1) ? y1 : y0);
            pa[1] = f2tf((t & 1) ? y3 : y2);
            pa[2] = f2tf((t & 1) ? z1 : z0);
            pa[3] = f2tf((t & 1) ? z3 : z2);

            uint32_t bv[8][2];
            #pragma unroll
            for (int p = 0; p < 4; p++)
                ldsm4(bv[2*p][0], bv[2*p][1], bv[2*p+1][0], bv[2*p+1][1],
                      Vt0 + (uint32_t)(p * 16 * KST + kk * 8) * 4 + f_lo);
            #pragma unroll
            for (int na = 0; na < 8; na++)
                mma8(o[na], pa, bv[na]);
        }
        __syncthreads();
    }

    l0 += __shfl_xor_sync(0xffffffffu, l0, 1);
    l0 += __shfl_xor_sync(0xffffffffu, l0, 2);
    l1 += __shfl_xor_sync(0xffffffffu, l1, 1);
    l1 += __shfl_xor_sync(0xffffffffu, l1, 2);
    const float i0 = 1.f / l0, i1 = 1.f / l1;

    float* orow0 = outp + (size_t)(b*SEQ + row0) * DIM + h*DH;
    float* orow1 = orow0 + 8*DIM;
    #pragma unroll
    for (int na = 0; na < 8; na++) {
        *(float2*)&orow0[na*8 + 2*t] = make_float2(o[na][0]*i0, o[na][1]*i0);
        *(float2*)&orow1[na*8 + 2*t] = make_float2(o[na][2]*i1, o[na][3]*i1);
    }
}

// ---------------------------------------------------------------------------
extern "C" void kernel_launch(void* const* d_in, const int* in_sizes, int n_in,
                              void* d_out, int out_size)
{
    const float* x     = (const float*)d_in[0];
    const float* W_qkv = (const float*)d_in[1];
    const float* W_out = (const float*)d_in[2];
    float*       out   = (float*)d_out;

    float* qkv  = nullptr;
    float* attn = nullptr;
    cudaGetSymbolAddress((void**)&qkv,  g_qkv);
    cudaGetSymbolAddress((void**)&attn, g_attn);

    // 1) qkv = x @ W_qkv^T
    gemm_lds<<<dim3(QKVCOL/128, MROWS/128), 128>>>(x, W_qkv, qkv, MROWS, QKVCOL, DIM);
    // 2) causal attention
    attn_tf32<<<dim3(SEQ/128, BATCH*HEADS), 256>>>(qkv, attn);
    // 3) out = attn @ W_out^T
    gemm_lds<<<dim3(DIM/128, MROWS/128), 128>>>(attn, W_out, out, MROWS, DIM, DIM);
}

// round 8
// speedup vs baseline: 3.4928x; 1.1178x over previous
#include <cuda_runtime.h>
#include <math.h>
#include <stdint.h>

#define SEQ    2048
#define BATCH  2
#define DIM    1024
#define HEADS  16
#define DH     64
#define MROWS  (BATCH*SEQ)          // 4096
#define QKVCOL (3*DIM)              // 3072

__device__ float g_qkv [MROWS * QKVCOL];
__device__ float g_attn[MROWS * DIM];

// ---------------------------------------------------------------------------
__device__ __forceinline__ uint32_t f2tf(float x){
    uint32_t r; asm("cvt.rna.tf32.f32 %0, %1;" : "=r"(r) : "f"(x)); return r;
}
__device__ __forceinline__ uint32_t smem_u32(const void* p){
    return (uint32_t)__cvta_generic_to_shared(p);
}
__device__ __forceinline__ void mma8(float* c, const uint32_t* a, const uint32_t* b){
    asm volatile("mma.sync.aligned.m16n8k8.row.col.f32.tf32.tf32.f32 "
        "{%0,%1,%2,%3}, {%4,%5,%6,%7}, {%8,%9}, {%0,%1,%2,%3};"
        : "+f"(c[0]),"+f"(c[1]),"+f"(c[2]),"+f"(c[3])
        : "r"(a[0]),"r"(a[1]),"r"(a[2]),"r"(a[3]),"r"(b[0]),"r"(b[1]));
}
__device__ __forceinline__ void ldsm4(uint32_t& r0, uint32_t& r1, uint32_t& r2, uint32_t& r3,
                                      uint32_t addr){
    asm volatile("ldmatrix.sync.aligned.m8n8.x4.shared.b16 {%0,%1,%2,%3}, [%4];"
        : "=r"(r0),"=r"(r1),"=r"(r2),"=r"(r3) : "r"(addr));
}

// ---------------------------------------------------------------------------
// tf32 GEMM: C[M,N] = A[M,K] @ B[N,K]^T.
// CTA 128x128, 256 threads (8 warps, 4x2), warp tile 32x64, ldmatrix frags,
// double-buffered smem, 2 CTAs/SM.
// ---------------------------------------------------------------------------
#define GST 20

__global__ void __launch_bounds__(256,2) gemm_lds(const float* __restrict__ A,
                                                  const float* __restrict__ B,
                                                  float* __restrict__ C,
                                                  int M, int N, int K)
{
    __shared__ uint32_t As[2][128*GST];
    __shared__ uint32_t Bs[2][128*GST];

    const int tid  = threadIdx.x;
    const int lane = tid & 31, wid = tid >> 5;
    const int g = lane >> 2, t = lane & 3;
    const int wm = wid & 3, wn = wid >> 2;
    const int bm = blockIdx.y * 128, bn = blockIdx.x * 128;

    const uint32_t As0 = smem_u32(As), Bs0 = smem_u32(Bs);
    const uint32_t a_lo = ((((lane & 7) + ((lane >> 3) & 1) * 8) * GST) + (lane >> 4) * 4) * 4;
    const uint32_t b_lo = ((((lane & 7) + ((lane >> 4) & 1) * 8) * GST) + ((lane >> 3) & 1) * 4) * 4;

    // fill mapping: thread owns row tid>>1, k-offset (tid&1)*8 (2 float4 per matrix)
    const int frow = tid >> 1, fko = (tid & 1) * 8;
    const float* Ag = A + (size_t)(bm + frow) * K + fko;
    const float* Bg = B + (size_t)(bn + frow) * K + fko;
    const uint32_t sA = As0 + (uint32_t)(frow * GST + fko) * 4;
    const uint32_t sB = Bs0 + (uint32_t)(frow * GST + fko) * 4;

    float acc[2][8][4] = {};
    const int NC = K / 16;

    float4 ra[2], rb[2];
    #pragma unroll
    for (int i = 0; i < 2; i++) { ra[i] = ((const float4*)Ag)[i]; rb[i] = ((const float4*)Bg)[i]; }
    #pragma unroll
    for (int i = 0; i < 2; i++) {
        asm volatile("st.shared.v4.b32 [%0], {%1,%2,%3,%4};" :: "r"(sA + i*16),
            "r"(f2tf(ra[i].x)),"r"(f2tf(ra[i].y)),"r"(f2tf(ra[i].z)),"r"(f2tf(ra[i].w)));
        asm volatile("st.shared.v4.b32 [%0], {%1,%2,%3,%4};" :: "r"(sB + i*16),
            "r"(f2tf(rb[i].x)),"r"(f2tf(rb[i].y)),"r"(f2tf(rb[i].z)),"r"(f2tf(rb[i].w)));
    }
    __syncthreads();

    for (int c = 0; c < NC; c++) {
        const int buf = c & 1;
        const uint32_t abase = As0 + (uint32_t)buf * (128*GST*4) + (uint32_t)(wm * 32 * GST) * 4;
        const uint32_t bbase = Bs0 + (uint32_t)buf * (128*GST*4) + (uint32_t)(wn * 64 * GST) * 4;

        if (c + 1 < NC) {
            const float* Ag2 = Ag + (c + 1) * 16;
            const float* Bg2 = Bg + (c + 1) * 16;
            #pragma unroll
            for (int i = 0; i < 2; i++) { ra[i] = ((const float4*)Ag2)[i]; rb[i] = ((const float4*)Bg2)[i]; }
        }

        #pragma unroll
        for (int ks = 0; ks < 2; ks++) {
            uint32_t af[2][4], bf[8][2];
            #pragma unroll
            for (int ma = 0; ma < 2; ma++)
                ldsm4(af[ma][0], af[ma][1], af[ma][2], af[ma][3],
                      abase + (uint32_t)(ma * 16 * GST + ks * 8) * 4 + a_lo);
            #pragma unroll
            for (int p = 0; p < 4; p++)
                ldsm4(bf[2*p][0], bf[2*p][1], bf[2*p+1][0], bf[2*p+1][1],
                      bbase + (uint32_t)(p * 16 * GST + ks * 8) * 4 + b_lo);
            #pragma unroll
            for (int ma = 0; ma < 2; ma++)
                #pragma unroll
                for (int nb = 0; nb < 8; nb++)
                    mma8(acc[ma][nb], af[ma], bf[nb]);
        }

        if (c + 1 < NC) {
            const uint32_t dA = sA + (uint32_t)((buf ^ 1) * 128 * GST) * 4;
            const uint32_t dB = sB + (uint32_t)((buf ^ 1) * 128 * GST) * 4;
            #pragma unroll
            for (int i = 0; i < 2; i++) {
                asm volatile("st.shared.v4.b32 [%0], {%1,%2,%3,%4};" :: "r"(dA + i*16),
                    "r"(f2tf(ra[i].x)),"r"(f2tf(ra[i].y)),"r"(f2tf(ra[i].z)),"r"(f2tf(ra[i].w)));
                asm volatile("st.shared.v4.b32 [%0], {%1,%2,%3,%4};" :: "r"(dB + i*16),
                    "r"(f2tf(rb[i].x)),"r"(f2tf(rb[i].y)),"r"(f2tf(rb[i].z)),"r"(f2tf(rb[i].w)));
            }
        }
        __syncthreads();
    }

    #pragma unroll
    for (int ma = 0; ma < 2; ma++) {
        const int r0 = bm + wm*32 + ma*16 + g;
        #pragma unroll
        for (int nb = 0; nb < 8; nb++) {
            const int c0 = bn + wn*64 + nb*8 + 2*t;
            *(float2*)&C[(size_t)r0     * N + c0] = make_float2(acc[ma][nb][0], acc[ma][nb][1]);
            *(float2*)&C[(size_t)(r0+8) * N + c0] = make_float2(acc[ma][nb][2], acc[ma][nb][3]);
        }
    }
}

// ---------------------------------------------------------------------------
// Flash attention, tf32 mma.sync + ldmatrix, register-prefetched KV tiles.
// ---------------------------------------------------------------------------
#define KST 68

__global__ void __launch_bounds__(256) attn_tf32(const float* __restrict__ qkv,
                                                 float* __restrict__ outp)
{
    __shared__ uint32_t sh[2*64*KST];
    float*    Qs = (float*)sh;
    uint32_t* Ks = sh;                          // [64 kv][KST]
    uint32_t* Vt = sh + 64*KST;                 // [64 dh][KST] (transposed)

    const int tid = threadIdx.x;
    const int lane = tid & 31, wid = tid >> 5;
    const int g = lane >> 2, t = lane & 3;
    const int bh = blockIdx.y, b = bh >> 4, h = bh & 15;
    const int q0 = blockIdx.x * 128;
    const float* base = qkv + (size_t)b * SEQ * QKVCOL;

    const uint32_t Ks0 = smem_u32(Ks), Vt0 = smem_u32(Vt);
    const uint32_t f_lo = ((((lane & 7) + ((lane >> 4) & 1) * 8) * KST) + ((lane >> 3) & 1) * 4) * 4;

    // stage Q raw into smem
    {
        const int r = tid >> 1, f0 = (tid & 1) * 32;
        const float* qr = base + (size_t)(q0 + r) * QKVCOL + h*DH + f0;
        float* dst = Qs + r*KST + f0;
        #pragma unroll
        for (int i = 0; i < 8; i++) ((float4*)dst)[i] = ((const float4*)qr)[i];
    }
    __syncthreads();

    uint32_t qf[8][4];
    {
        const float* qb = Qs + (wid*16 + g) * KST;
        #pragma unroll
        for (int kk = 0; kk < 8; kk++) {
            qf[kk][0] = f2tf(qb[kk*8 + t]             * 0.125f);
            qf[kk][1] = f2tf(qb[8*KST + kk*8 + t]     * 0.125f);
            qf[kk][2] = f2tf(qb[kk*8 + t + 4]         * 0.125f);
            qf[kk][3] = f2tf(qb[8*KST + kk*8 + t + 4] * 0.125f);
        }
    }
    __syncthreads();

    float o[8][4] = {};
    float m0 = -INFINITY, m1 = -INFINITY, l0 = 0.f, l1 = 0.f;
    const int row0 = q0 + wid*16 + g;
    const int ntiles = q0/64 + 2;

    // fill mapping: r = tid&63, c0 = (tid>>6)*16
    const int fr = tid & 63, fc = (tid >> 6) * 16;
    const float* Kg = base + (size_t)fr * QKVCOL +     DIM + h*DH + fc;
    const float* Vg = base + (size_t)fr * QKVCOL + 2 * DIM + h*DH + fc;
    const size_t tstep = (size_t)64 * QKVCOL;

    float4 rk[4], rv[4];
    #pragma unroll
    for (int i = 0; i < 4; i++) { rk[i] = ((const float4*)Kg)[i]; rv[i] = ((const float4*)Vg)[i]; }

    for (int kt = 0; kt < ntiles; kt++) {
        // commit prefetched tile to smem
        {
            uint32_t* kd = Ks + fr*KST + fc;
            #pragma unroll
            for (int i = 0; i < 4; i++) {
                ((uint4*)kd)[i] = make_uint4(f2tf(rk[i].x),f2tf(rk[i].y),f2tf(rk[i].z),f2tf(rk[i].w));
                Vt[(fc + 4*i    )*KST + fr] = f2tf(rv[i].x);
                Vt[(fc + 4*i + 1)*KST + fr] = f2tf(rv[i].y);
                Vt[(fc + 4*i + 2)*KST + fr] = f2tf(rv[i].z);
                Vt[(fc + 4*i + 3)*KST + fr] = f2tf(rv[i].w);
            }
        }
        __syncthreads();

        // prefetch next tile (overlaps with compute below)
        if (kt + 1 < ntiles) {
            const float* Kg2 = Kg + (size_t)(kt + 1) * tstep;
            const float* Vg2 = Vg + (size_t)(kt + 1) * tstep;
            #pragma unroll
            for (int i = 0; i < 4; i++) { rk[i] = ((const float4*)Kg2)[i]; rv[i] = ((const float4*)Vg2)[i]; }
        }

        // ---- S = Q @ K^T ----
        float s[8][4] = {};
        #pragma unroll
        for (int kk = 0; kk < 8; kk++) {
            uint32_t bk[8][2];
            #pragma unroll
            for (int p = 0; p < 4; p++)
                ldsm4(bk[2*p][0], bk[2*p][1], bk[2*p+1][0], bk[2*p+1][1],
                      Ks0 + (uint32_t)(p * 16 * KST + kk * 8) * 4 + f_lo);
            #pragma unroll
            for (int nb = 0; nb < 8; nb++)
                mma8(s[nb], qf[kk], bk[nb]);
        }

        // ---- causal mask + online softmax ----
        const int colbase = kt*64 + 2*t;
        float t0 = -INFINITY, t1 = -INFINITY;
        #pragma unroll
        for (int na = 0; na < 8; na++) {
            const int c = colbase + na*8;
            if (c     > row0)     s[na][0] = -INFINITY;
            if (c + 1 > row0)     s[na][1] = -INFINITY;
            if (c     > row0 + 8) s[na][2] = -INFINITY;
            if (c + 1 > row0 + 8) s[na][3] = -INFINITY;
            t0 = fmaxf(t0, fmaxf(s[na][0], s[na][1]));
            t1 = fmaxf(t1, fmaxf(s[na][2], s[na][3]));
        }
        t0 = fmaxf(t0, __shfl_xor_sync(0xffffffffu, t0, 1));
        t0 = fmaxf(t0, __shfl_xor_sync(0xffffffffu, t0, 2));
        t1 = fmaxf(t1, __shfl_xor_sync(0xffffffffu, t1, 1));
        t1 = fmaxf(t1, __shfl_xor_sync(0xffffffffu, t1, 2));

        const float mn0 = fmaxf(m0, t0), mn1 = fmaxf(m1, t1);
        const float sc0 = __expf(m0 - mn0), sc1 = __expf(m1 - mn1);
        m0 = mn0; m1 = mn1; l0 *= sc0; l1 *= sc1;

        #pragma unroll
        for (int na = 0; na < 8; na++) {
            o[na][0] *= sc0; o[na][1] *= sc0; o[na][2] *= sc1; o[na][3] *= sc1;
            s[na][0] = __expf(s[na][0] - m0);
            s[na][1] = __expf(s[na][1] - m0);
            s[na][2] = __expf(s[na][2] - m1);
            s[na][3] = __expf(s[na][3] - m1);
            l0 += s[na][0] + s[na][1];
            l1 += s[na][2] + s[na][3];
        }

        // ---- O += P @ V ----
        #pragma unroll
        for (int kk = 0; kk < 8; kk++) {
            const int srcA = (lane & ~3) | (t >> 1);
            const int srcB = srcA + 2;
            float y0 = __shfl_sync(0xffffffffu, s[kk][0], srcA);
            float y1 = __shfl_sync(0xffffffffu, s[kk][1], srcA);
            float y2 = __shfl_sync(0xffffffffu, s[kk][2], srcA);
            float y3 = __shfl_sync(0xffffffffu, s[kk][3], srcA);
            float z0 = __shfl_sync(0xffffffffu, s[kk][0], srcB);
            float z1 = __shfl_sync(0xffffffffu, s[kk][1], srcB);
            float z2 = __shfl_sync(0xffffffffu, s[kk][2], srcB);
            float z3 = __shfl_sync(0xffffffffu, s[kk][3], srcB);
            uint32_t pa[4];
            pa[0] = f2tf((t & 1) ? y1 : y0);
            pa[1] = f2tf((t & 1) ? y3 : y2);
            pa[2] = f2tf((t & 1) ? z1 : z0);
            pa[3] = f2tf((t & 1) ? z3 : z2);

            uint32_t bv[8][2];
            #pragma unroll
            for (int p = 0; p < 4; p++)
                ldsm4(bv[2*p][0], bv[2*p][1], bv[2*p+1][0], bv[2*p+1][1],
                      Vt0 + (uint32_t)(p * 16 * KST + kk * 8) * 4 + f_lo);
            #pragma unroll
            for (int na = 0; na < 8; na++)
                mma8(o[na], pa, bv[na]);
        }
        __syncthreads();
    }

    l0 += __shfl_xor_sync(0xffffffffu, l0, 1);
    l0 += __shfl_xor_sync(0xffffffffu, l0, 2);
    l1 += __shfl_xor_sync(0xffffffffu, l1, 1);
    l1 += __shfl_xor_sync(0xffffffffu, l1, 2);
    const float i0 = 1.f / l0, i1 = 1.f / l1;

    float* orow0 = outp + (size_t)(b*SEQ + row0) * DIM + h*DH;
    float* orow1 = orow0 + 8*DIM;
    #pragma unroll
    for (int na = 0; na < 8; na++) {
        *(float2*)&orow0[na*8 + 2*t] = make_float2(o[na][0]*i0, o[na][1]*i0);
        *(float2*)&orow1[na*8 + 2*t] = make_float2(o[na][2]*i1, o[na][3]*i1);
    }
}

// ---------------------------------------------------------------------------
extern "C" void kernel_launch(void* const* d_in, const int* in_sizes, int n_in,
                              void* d_out, int out_size)
{
    const float* x     = (const float*)d_in[0];
    const float* W_qkv = (const float*)d_in[1];
    const float* W_out = (const float*)d_in[2];
    float*       out   = (float*)d_out;

    float* qkv  = nullptr;
    float* attn = nullptr;
    cudaGetSymbolAddress((void**)&qkv,  g_qkv);
    cudaGetSymbolAddress((void**)&attn, g_attn);

    // 1) qkv = x @ W_qkv^T
    gemm_lds<<<dim3(QKVCOL/128, MROWS/128), 256>>>(x, W_qkv, qkv, MROWS, QKVCOL, DIM);
    // 2) causal attention
    attn_tf32<<<dim3(SEQ/128, BATCH*HEADS), 256>>>(qkv, attn);
    // 3) out = attn @ W_out^T
    gemm_lds<<<dim3(DIM/128, MROWS/128), 256>>>(attn, W_out, out, MROWS, DIM, DIM);
}